// round 15
// baseline (speedup 1.0000x reference)
#include <cuda_runtime.h>
#include <cuda_bf16.h>
#include <cstdint>

// ---------------------------------------------------------------------------
// bPC SNN, 25 steps. Round 15: HMMA bf16x3 6-product GEMM + z-batching.
// (Byte-identical resubmit of R14 — broker "container failed twice" before
// compile; same flake as R9/R12, both of which passed and WON on resubmit.)
//   - Numerics identical to R13 (proven: rel_err 5.22e-6): bf16x3 split,
//     6 products hh,hm,mh,hl,lh,mm, fp32 accumulate.
//   - Independent GEMMs batched into one launch via blockIdx.z TG table
//     (Phase-A x3, Phase-B x4) -> kills wave quantization (128 CTA / 148 SM
//     serial waves).
//   - Depth-3 cp.async pipeline with a single __syncthreads per chunk
//     (reload target at c+2 was last read at c-1; top barrier of c covers it).
//   - Setup ordered so profiled launch #5 is gemm_mma (ncu visibility).
//   - Kept: fused split emission (epilogue/reduce/lif), split-K 4x/8x for
//     eg0/ed4, fragment-sharing inner loop, 80B-pitch smem.
// ---------------------------------------------------------------------------

#define S_LAYER (512 * 4096)
#define OUT_LD  26112

typedef __nv_bfloat16 bf16;

// ---- device storage -------------------------------------------------------
__device__ float g_state[9 * S_LAYER];          // j1..3 | v1..3 | x1..3
__device__ float g_tin[3 * S_LAYER];            // injected currents
__device__ float g_c1h[S_LAYER];                // 0.5 * x_data @ V0^T
__device__ float g_c2h[S_LAYER];                // 0.5 * y_target @ W3^T
__device__ bf16  g_w[459276288];                // weight splits (direct+T), x3
__device__ bf16  g_act[46399488];               // activation splits, x3
__device__ bf16  g_io[2359296];                 // xd/yt splits, x3
__device__ float g_pA[4 * 512 * 1024];          // eg0 split-K partials
__device__ float g_pB[8 * 512 * 512];           // ed4 split-K partials

// ---- weight slab offsets (elements); each slab = [3][N][K] ----------------
#define OFF_W0d   0L            // [1024,4096]
#define OFF_V0d   12582912L     // [4096,1024]
#define OFF_W1d   25165824L     // [4096,4096]
#define OFF_V1d   75497472L
#define OFF_W2d   125829120L
#define OFF_V2d   176160768L
#define OFF_W3d   226492416L    // [4096,512]
#define OFF_V3d   232783872L    // [512,4096]
#define OFF_Wt0   239075328L    // [4096,1024]
#define OFF_Wt1   251658240L    // [4096,4096]
#define OFF_Vt1   301989888L
#define OFF_Wt2   352321536L
#define OFF_Vt2   402653184L
#define OFF_Vt3   452984832L    // [4096,512]

// activation slab offsets; each slab = [3][512][K]
#define AOFF_EG0  0L            // [512,1024]
#define AOFF_EG1  1572864L      // [512,4096]
#define AOFF_ED2  7864320L
#define AOFF_EG2  14155776L
#define AOFF_ED3  20447232L
#define AOFF_ED4  26738688L     // [512,512]
#define AOFF_X1   27525120L     // [512,4096]
#define AOFF_X2   33816576L
#define AOFF_X3   40108032L

// ---------------------------------------------------------------------------
__device__ __forceinline__ uint32_t smem_u32(const void* p) {
    uint32_t a;
    asm("{ .reg .u64 t; cvta.to.shared.u64 t, %1; cvt.u32.u64 %0, t; }"
        : "=r"(a) : "l"(p));
    return a;
}
#define CP16(dst, src) \
    asm volatile("cp.async.cg.shared.global [%0], [%1], 16;" \
                 :: "r"(dst), "l"(src) : "memory")
#define CP_COMMIT() asm volatile("cp.async.commit_group;" ::: "memory")
#define CP_WAIT1()  asm volatile("cp.async.wait_group 1;" ::: "memory")
#define CP_WAIT0()  asm volatile("cp.async.wait_group 0;" ::: "memory")

__device__ __forceinline__ void ldsm_x4(uint32_t (&r)[4], uint32_t addr) {
    asm volatile("ldmatrix.sync.aligned.m8n8.x4.shared.b16 {%0,%1,%2,%3}, [%4];"
                 : "=r"(r[0]), "=r"(r[1]), "=r"(r[2]), "=r"(r[3]) : "r"(addr));
}
__device__ __forceinline__ void mma_bf16(float (&c)[4], const uint32_t (&a)[4],
                                         uint32_t b0, uint32_t b1) {
    asm volatile(
        "mma.sync.aligned.m16n8k16.row.col.f32.bf16.bf16.f32 "
        "{%0,%1,%2,%3}, {%4,%5,%6,%7}, {%8,%9}, {%0,%1,%2,%3};"
        : "+f"(c[0]), "+f"(c[1]), "+f"(c[2]), "+f"(c[3])
        : "r"(a[0]), "r"(a[1]), "r"(a[2]), "r"(a[3]), "r"(b0), "r"(b1));
}

// ---------------------------------------------------------------------------
// GEMM: C[512,N] = alpha * sum6( A_s @ B_s^T ) + g0*aux0 + g1*aux1
//       (+ optional bf16x3 split emission of C, + optional split-K)
// A slabs: [3][512][*] bf16, k-contiguous rows. B slabs: [3][N][*] bf16.
// Batched: grid.z indexes a TG table (or K-chunks when g[0].kc != 0).
// ---------------------------------------------------------------------------
struct TG {
    const bf16 *A1, *B1, *A2, *B2;
    long sA1, sB1, sA2, sB2;        // per-split slab strides
    int  lda1, ldb1, lda2, ldb2;    // row strides (elements)
    int  K1, K2;
    float* C; int ldc;
    const float* aux0; int ld0; float g0;
    const float* aux1; int ld1; float g1;
    float alpha;
    bf16* so; long sso; int ldso;   // optional split output [3][512][N]
    int  kc; long czstride;         // split-K: chunk len / C z-stride
};
struct TGB { TG g[4]; };

#define TILE_B   10240            // 128 rows x 80B (32 bf16 + 8B pad)
#define STAGE_B  (6 * TILE_B)     // A0,A1,A2,B0,B1,B2
#define SMEM_MM  (3 * STAGE_B)    // 3-stage pipeline = 184320 B

__global__ __launch_bounds__(256, 1) void gemm_mma(TGB pb) {
    extern __shared__ char smem[];
    const TG& p = pb.g[pb.g[0].kc ? 0 : blockIdx.z];
    const uint32_t sb = smem_u32(smem);
    const int tid  = threadIdx.x;
    const int wid  = tid >> 5;
    const int lane = tid & 31;
    const int bm   = blockIdx.y * 128;
    const int bn   = blockIdx.x * 128;
    const int wm   = (wid & 1) * 64;
    const int wn   = (wid >> 1) * 32;

    const bf16* LA1 = p.A1;
    const bf16* LB1 = p.B1;
    int    LK1 = p.K1;
    float* C   = p.C;
    if (p.kc) {
        LA1 += (long)blockIdx.z * p.kc;
        LB1 += (long)blockIdx.z * p.kc;
        LK1  = p.kc;
        C   += (long)blockIdx.z * p.czstride;
    }
    const int nk1 = LK1 >> 5;
    const int nk  = (LK1 + p.K2) >> 5;

    float acc[4][4][4];
#pragma unroll
    for (int i = 0; i < 4; i++)
#pragma unroll
        for (int j = 0; j < 4; j++)
#pragma unroll
            for (int q = 0; q < 4; q++) acc[i][j][q] = 0.0f;

    auto load_chunk = [&](int c, int s) {
        const bool seg2 = (c >= nk1);
        const bf16* Ab = seg2 ? p.A2 : LA1;
        const bf16* Bb = seg2 ? p.B2 : LB1;
        const long  sA = seg2 ? p.sA2 : p.sA1;
        const long  sB = seg2 ? p.sB2 : p.sB1;
        const int   la = seg2 ? p.lda2 : p.lda1;
        const int   lb = seg2 ? p.ldb2 : p.ldb1;
        const long  kcoff = (long)(seg2 ? c - nk1 : c) * 32;
        const uint32_t base = sb + s * STAGE_B;
#pragma unroll
        for (int sp = 0; sp < 3; sp++) {
            const bf16* ga = Ab + sp * sA + kcoff;
            const bf16* gb = Bb + sp * sB + kcoff;
#pragma unroll
            for (int i = 0; i < 2; i++) {
                const int id  = tid + i * 256;
                const int row = id >> 2;
                const int seg = (id & 3) * 16;
                CP16(base + sp * TILE_B + row * 80 + seg,
                     (const char*)(ga + (long)(bm + row) * la) + seg);
                CP16(base + (3 + sp) * TILE_B + row * 80 + seg,
                     (const char*)(gb + (long)(bn + row) * lb) + seg);
            }
        }
        CP_COMMIT();
    };

    load_chunk(0, 0);
    load_chunk(1, 1);

#define LDA(F, abase, kk)                                                      \
    _Pragma("unroll")                                                          \
    for (int i = 0; i < 4; i++)                                                \
        ldsm_x4(F[i], (abase) + (uint32_t)(wm + 16 * i + (lane & 15)) * 80     \
                        + (kk) * 32 + (lane >> 4) * 16);
#define LDB(F, bbase, kk)                                                      \
    _Pragma("unroll")                                                          \
    for (int h = 0; h < 2; h++)                                                \
        ldsm_x4(F[h], (bbase) + (uint32_t)(wn + 16 * h + 8 * ((lane >> 4) & 1) \
                        + (lane & 7)) * 80 + (kk) * 32 + ((lane >> 3) & 1) * 16);
#define MMAS(AF, BF)                                                           \
    _Pragma("unroll")                                                          \
    for (int i = 0; i < 4; i++)                                                \
        _Pragma("unroll")                                                      \
        for (int j = 0; j < 4; j++)                                            \
            mma_bf16(acc[i][j], AF[i], BF[j >> 1][(j & 1) * 2],                \
                     BF[j >> 1][(j & 1) * 2 + 1]);

    for (int c = 0; c < nk; c++) {
        if (c + 1 < nk) CP_WAIT1(); else CP_WAIT0();
        __syncthreads();
        if (c + 2 < nk) load_chunk(c + 2, (c + 2) % 3);

        const uint32_t base = sb + (c % 3) * STAGE_B;
        const uint32_t a0 = base,              a1 = base + TILE_B,     a2 = base + 2 * TILE_B;
        const uint32_t b0 = base + 3 * TILE_B, b1 = base + 4 * TILE_B, b2 = base + 5 * TILE_B;
#pragma unroll
        for (int kk = 0; kk < 2; kk++) {
            uint32_t Ah[4][4], Am[4][4], Al[4][4], Bh[2][4], Bm[2][4], Bl[2][4];
            LDA(Ah, a0, kk); LDB(Bh, b0, kk);
            MMAS(Ah, Bh);                       // hi * hi
            LDB(Bm, b1, kk);
            MMAS(Ah, Bm);                       // hi * mid
            LDA(Am, a1, kk);
            MMAS(Am, Bh);                       // mid * hi
            LDB(Bl, b2, kk);
            MMAS(Ah, Bl);                       // hi * lo
            LDA(Al, a2, kk);
            MMAS(Al, Bh);                       // lo * hi
            MMAS(Am, Bm);                       // mid * mid
        }
        // no trailing sync: stage (c+2)%3 was last read at chunk c-1, which
        // every warp finished before passing this chunk's top barrier.
    }
#undef LDA
#undef LDB
#undef MMAS

    // ---- epilogue ---------------------------------------------------------
    const int r0    = lane >> 2;
    const int cpair = (lane & 3) * 2;
#pragma unroll
    for (int i = 0; i < 4; i++) {
        const long gr = bm + wm + 16 * i + r0;
#pragma unroll
        for (int j = 0; j < 4; j++) {
            const int gc = bn + wn + 8 * j + cpair;
            float v[4];
            v[0] = p.alpha * acc[i][j][0];
            v[1] = p.alpha * acc[i][j][1];
            v[2] = p.alpha * acc[i][j][2];
            v[3] = p.alpha * acc[i][j][3];
            if (p.aux0) {
                const float2 u0 = *(const float2*)(p.aux0 + gr * p.ld0 + gc);
                const float2 u1 = *(const float2*)(p.aux0 + (gr + 8) * p.ld0 + gc);
                v[0] += p.g0 * u0.x; v[1] += p.g0 * u0.y;
                v[2] += p.g0 * u1.x; v[3] += p.g0 * u1.y;
            }
            if (p.aux1) {
                const float2 u0 = *(const float2*)(p.aux1 + gr * p.ld1 + gc);
                const float2 u1 = *(const float2*)(p.aux1 + (gr + 8) * p.ld1 + gc);
                v[0] += p.g1 * u0.x; v[1] += p.g1 * u0.y;
                v[2] += p.g1 * u1.x; v[3] += p.g1 * u1.y;
            }
            *(float2*)(C + gr * p.ldc + gc)       = make_float2(v[0], v[1]);
            *(float2*)(C + (gr + 8) * p.ldc + gc) = make_float2(v[2], v[3]);
            if (p.so) {                         // fused bf16x3 split emission
                bf16 h[4], m[4], l[4];
#pragma unroll
                for (int q = 0; q < 4; q++) {
                    h[q] = __float2bfloat16(v[q]);
                    const float r1 = v[q] - __bfloat162float(h[q]);
                    m[q] = __float2bfloat16(r1);
                    l[q] = __float2bfloat16(r1 - __bfloat162float(m[q]));
                }
                __nv_bfloat162 P;
                P.x = h[0]; P.y = h[1];
                *(__nv_bfloat162*)(p.so + gr * p.ldso + gc) = P;
                P.x = h[2]; P.y = h[3];
                *(__nv_bfloat162*)(p.so + (gr + 8) * p.ldso + gc) = P;
                P.x = m[0]; P.y = m[1];
                *(__nv_bfloat162*)(p.so + p.sso + gr * p.ldso + gc) = P;
                P.x = m[2]; P.y = m[3];
                *(__nv_bfloat162*)(p.so + p.sso + (gr + 8) * p.ldso + gc) = P;
                P.x = l[0]; P.y = l[1];
                *(__nv_bfloat162*)(p.so + 2 * p.sso + gr * p.ldso + gc) = P;
                P.x = l[2]; P.y = l[3];
                *(__nv_bfloat162*)(p.so + 2 * p.sso + (gr + 8) * p.ldso + gc) = P;
            }
        }
    }
}

// ---------------------------------------------------------------------------
// Split-K reduce: e = 0.5*ref - 0.5*sum_z P[z]; write float + bf16x3 splits
// ---------------------------------------------------------------------------
__global__ void reduce_k(const float* __restrict__ P, int nsplit,
                         const float* __restrict__ ref, int ldref,
                         float* __restrict__ out, int outoff, int N,
                         bf16* __restrict__ so, long sso) {
    const int idx = blockIdx.x * blockDim.x + threadIdx.x;
    if (idx >= 512 * N) return;
    const int  b    = idx / N;
    const int  f    = idx - b * N;
    const long slab = (long)512 * N;
    float s = 0.0f;
    for (int z = 0; z < nsplit; ++z) s += P[z * slab + idx];
    const float e = 0.5f * ref[(long)b * ldref + f] - 0.5f * s;
    out[(long)b * OUT_LD + outoff + f] = e;
    const bf16 h = __float2bfloat16(e);
    const float r1 = e - __bfloat162float(h);
    const bf16 m = __float2bfloat16(r1);
    so[idx]           = h;
    so[sso + idx]     = m;
    so[2 * sso + idx] = __float2bfloat16(r1 - __bfloat162float(m));
}

// ---------------------------------------------------------------------------
// splitters (weights / inputs, once per launch)
// ---------------------------------------------------------------------------
__global__ void split_k(const float* __restrict__ in, int ld, int rows, int cols,
                        bf16* __restrict__ out) {
    const long n = (long)rows * cols;
    const long idx = (long)blockIdx.x * blockDim.x + threadIdx.x;
    if (idx >= n) return;
    const int r = (int)(idx / cols), c = (int)(idx - (long)r * cols);
    const float a = in[(long)r * ld + c];
    const bf16 h = __float2bfloat16(a);
    const float f1 = a - __bfloat162float(h);
    const bf16 m = __float2bfloat16(f1);
    out[idx]         = h;
    out[n + idx]     = m;
    out[2 * n + idx] = __float2bfloat16(f1 - __bfloat162float(m));
}
__global__ void splitT_k(const float* __restrict__ in, int ldin, int K, int N,
                         bf16* __restrict__ out) {
    const long n = (long)N * K;
    const long idx = (long)blockIdx.x * blockDim.x + threadIdx.x;
    if (idx >= n) return;
    const int nn = (int)(idx / K), k = (int)(idx - (long)nn * K);
    const float a = in[(long)k * ldin + nn];
    const bf16 h = __float2bfloat16(a);
    const float f1 = a - __bfloat162float(h);
    const bf16 m = __float2bfloat16(f1);
    out[idx]         = h;
    out[n + idx]     = m;
    out[2 * n + idx] = __float2bfloat16(f1 - __bfloat162float(m));
}

// ---------------------------------------------------------------------------
// LIF update; emits ed1/eg3 (float) and x1..3 bf16x3 splits
// ---------------------------------------------------------------------------
__global__ void lif_k(float* dout) {
    const long idx = (long)blockIdx.x * blockDim.x + threadIdx.x;
    if (idx >= 3L * S_LAYER) return;
    const int L = (int)(idx / S_LAYER);
    const int r = (int)(idx - (long)L * S_LAYER);

    const float tin = g_tin[idx];
    float j = g_state[idx];
    float v = g_state[3L * S_LAYER + idx];
    float x = g_state[6L * S_LAYER + idx];

    j = j + 0.25f * (tin - j);
    v = v + 0.05f * (j - v);
    const float spk = (v > 1.0f) ? 1.0f : 0.0f;
    v = v * (1.0f - spk);
    x = x * (1.0f - 0.025f) + spk;

    g_state[idx] = j;
    g_state[3L * S_LAYER + idx] = v;
    g_state[6L * S_LAYER + idx] = x;

    // x splits for phase-B GEMMs (slab [3][512][4096] per layer)
    const long xb = AOFF_X1 + (long)L * 6291456L + r;
    const bf16 h = __float2bfloat16(x);
    const float f1 = x - __bfloat162float(h);
    const bf16 m = __float2bfloat16(f1);
    g_act[xb]            = h;
    g_act[xb + 2097152L] = m;
    g_act[xb + 4194304L] = __float2bfloat16(f1 - __bfloat162float(m));

    if (L == 0) {                         // ed1 = 0.5*x1 - c1h
        const int b = r >> 12, f = r & 4095;
        dout[(long)b * OUT_LD + 13312 + f] = 0.5f * x - g_c1h[r];
    } else if (L == 2) {                  // eg3 = 0.5*x3 - c2h
        const int b = r >> 12, f = r & 4095;
        dout[(long)b * OUT_LD + 9216 + f] = 0.5f * x - g_c2h[r];
    }
}

__global__ void zero_k(float* dout) {
    const long n1 = 9L * S_LAYER;
    const long n2 = 27525120L;            // act EG0..ED4 region
    const long n3 = 512L * OUT_LD;
    for (long i = (long)blockIdx.x * blockDim.x + threadIdx.x; i < n1 + n2 + n3;
         i += (long)gridDim.x * blockDim.x) {
        if (i < n1)            g_state[i] = 0.0f;
        else if (i < n1 + n2)  g_act[i - n1] = __float2bfloat16(0.0f);
        else                   dout[i - n1 - n2] = 0.0f;
    }
}

// ---------------------------------------------------------------------------
static TG make_tg(const bf16* A1, long sA1, int lda1,
                  const bf16* B1, long sB1, int ldb1, int K1,
                  const bf16* A2, long sA2, int lda2,
                  const bf16* B2, long sB2, int ldb2, int K2,
                  float* C, int ldc,
                  const float* a0, int l0, float g0,
                  const float* a1, int l1, float g1,
                  float alpha,
                  bf16* so = nullptr, long sso = 0, int ldso = 0,
                  int kc = 0, long czstride = 0) {
    TG p;
    p.A1 = A1; p.sA1 = sA1; p.lda1 = lda1;
    p.B1 = B1; p.sB1 = sB1; p.ldb1 = ldb1; p.K1 = K1;
    p.A2 = A2 ? A2 : A1; p.sA2 = sA2; p.lda2 = lda2;
    p.B2 = B2 ? B2 : B1; p.sB2 = sB2; p.ldb2 = ldb2; p.K2 = K2;
    p.C = C; p.ldc = ldc;
    p.aux0 = a0; p.ld0 = l0; p.g0 = g0;
    p.aux1 = a1; p.ld1 = l1; p.g1 = g1;
    p.alpha = alpha;
    p.so = so; p.sso = sso; p.ldso = ldso;
    p.kc = kc; p.czstride = czstride;
    return p;
}

static void launch_batch(const TG* tg, int nz, int N) {
    TGB pb{};
    for (int z = 0; z < nz; z++) pb.g[z] = tg[z];
    dim3 grid(N / 128, 4, nz);
    gemm_mma<<<grid, 256, SMEM_MM>>>(pb);
}

static void launch_splitk(const TG& tg, int nsplit, int N) {
    TGB pb{};
    pb.g[0] = tg;
    dim3 grid(N / 128, 4, nsplit);
    gemm_mma<<<grid, 256, SMEM_MM>>>(pb);
}

extern "C" void kernel_launch(void* const* d_in, const int* in_sizes, int n_in,
                              void* d_out, int out_size) {
    (void)in_sizes; (void)n_in; (void)out_size;
    const float* xd = (const float*)d_in[0];   // (512, 1024)
    const float* yt = (const float*)d_in[1];   // (512, 512)
    const float* W0 = (const float*)d_in[2];
    const float* V0 = (const float*)d_in[3];
    const float* W1 = (const float*)d_in[4];
    const float* V1 = (const float*)d_in[5];
    const float* W2 = (const float*)d_in[6];
    const float* V2 = (const float*)d_in[7];
    const float* W3 = (const float*)d_in[8];
    const float* V3 = (const float*)d_in[9];
    float* out = (float*)d_out;

    cudaFuncSetAttribute(gemm_mma, cudaFuncAttributeMaxDynamicSharedMemorySize, SMEM_MM);

    float *st, *tin, *c1h, *c2h, *pA, *pB; bf16 *w, *act, *io;
    cudaGetSymbolAddress((void**)&st,  g_state);
    cudaGetSymbolAddress((void**)&tin, g_tin);
    cudaGetSymbolAddress((void**)&c1h, g_c1h);
    cudaGetSymbolAddress((void**)&c2h, g_c2h);
    cudaGetSymbolAddress((void**)&w,   g_w);
    cudaGetSymbolAddress((void**)&act, g_act);
    cudaGetSymbolAddress((void**)&io,  g_io);
    cudaGetSymbolAddress((void**)&pA,  g_pA);
    cudaGetSymbolAddress((void**)&pB,  g_pB);

    float* x1 = st + 6L * S_LAYER;
    float* x2 = st + 7L * S_LAYER;
    float* x3 = st + 8L * S_LAYER;
    float* t1 = tin;
    float* t2 = tin + S_LAYER;
    float* t3 = tin + 2L * S_LAYER;

    float* eg1 = out + 1024;
    float* eg2 = out + 5120;
    float* eg3 = out + 9216;     // written by lif_k
    float* ed1 = out + 13312;    // written by lif_k
    float* ed2 = out + 17408;
    float* ed3 = out + 21504;

    // ---- setup, ordered so launch #5 (ncu -s 5 -c 1) is a gemm_mma --------
    zero_k<<<2048, 256>>>(out);                                         // 0
    split_k<<<(512 * 1024 + 255) / 256, 256>>>(xd, 1024, 512, 1024, io);            // 1
    split_k<<<(512 * 512  + 255) / 256, 256>>>(yt, 512,  512, 512,  io + 1572864);  // 2
    split_k<<<(4096 * 1024 + 255) / 256, 256>>>(V0, 1024, 4096, 1024, w + OFF_V0d); // 3
    split_k<<<(4096 * 512  + 255) / 256, 256>>>(W3, 512,  4096, 512,  w + OFF_W3d); // 4
    {   // 5: c1h = 0.5 * xd @ V0^T   (N=4096, K=1024) — profiled launch
        TG g = make_tg(io, 524288, 1024, w + OFF_V0d, 4194304, 1024, 1024,
                       nullptr, 0, 0, nullptr, 0, 0, 0,
                       c1h, 4096, nullptr, 0, 0.f, nullptr, 0, 0.f, 0.5f);
        launch_batch(&g, 1, 4096);
    }
    {   // 6: c2h = 0.5 * yt @ W3^T   (N=4096, K=512)
        TG g = make_tg(io + 1572864, 262144, 512, w + OFF_W3d, 2097152, 512, 512,
                       nullptr, 0, 0, nullptr, 0, 0, 0,
                       c2h, 4096, nullptr, 0, 0.f, nullptr, 0, 0.f, 0.5f);
        launch_batch(&g, 1, 4096);
    }
    split_k<<<(1024 * 4096 + 255) / 256, 256>>>(W0, 4096, 1024, 4096, w + OFF_W0d);
    split_k<<<(4096 * 4096 + 255) / 256, 256>>>(W1, 4096, 4096, 4096, w + OFF_W1d);
    split_k<<<(4096 * 4096 + 255) / 256, 256>>>(V1, 4096, 4096, 4096, w + OFF_V1d);
    split_k<<<(4096 * 4096 + 255) / 256, 256>>>(W2, 4096, 4096, 4096, w + OFF_W2d);
    split_k<<<(4096 * 4096 + 255) / 256, 256>>>(V2, 4096, 4096, 4096, w + OFF_V2d);
    split_k<<<(512  * 4096 + 255) / 256, 256>>>(V3, 4096, 512,  4096, w + OFF_V3d);
    splitT_k<<<(4096 * 1024 + 255) / 256, 256>>>(W0, 4096, 1024, 4096, w + OFF_Wt0);
    splitT_k<<<(4096 * 4096 + 255) / 256, 256>>>(W1, 4096, 4096, 4096, w + OFF_Wt1);
    splitT_k<<<(4096 * 4096 + 255) / 256, 256>>>(V1, 4096, 4096, 4096, w + OFF_Vt1);
    splitT_k<<<(4096 * 4096 + 255) / 256, 256>>>(W2, 4096, 4096, 4096, w + OFF_Wt2);
    splitT_k<<<(4096 * 4096 + 255) / 256, 256>>>(V2, 4096, 4096, 4096, w + OFF_Vt2);
    splitT_k<<<(4096 * 512  + 255) / 256, 256>>>(V3, 4096, 512,  4096, w + OFF_Vt3);

    const int NUM_STEPS = 25;
    for (int t = 0; t < NUM_STEPS; t++) {
        // ---- Phase A: injected currents — ONE launch, z = 3 ----
        TG pa[3];
        // t1 = eg0@W0 + ed2@V1 - ed1 - eg1
        pa[0] = make_tg(act + AOFF_EG0, 524288, 1024, w + OFF_Wt0, 4194304, 1024, 1024,
                        act + AOFF_ED2, 2097152, 4096, w + OFF_Vt1, 16777216, 4096, 4096,
                        t1, 4096, ed1, OUT_LD, -1.f, eg1, OUT_LD, -1.f, 1.f);
        // t2 = eg1@W1 + ed3@V2 - ed2 - eg2
        pa[1] = make_tg(act + AOFF_EG1, 2097152, 4096, w + OFF_Wt1, 16777216, 4096, 4096,
                        act + AOFF_ED3, 2097152, 4096, w + OFF_Vt2, 16777216, 4096, 4096,
                        t2, 4096, ed2, OUT_LD, -1.f, eg2, OUT_LD, -1.f, 1.f);
        // t3 = eg2@W2 + ed4@V3 - ed3 - eg3
        pa[2] = make_tg(act + AOFF_EG2, 2097152, 4096, w + OFF_Wt2, 16777216, 4096, 4096,
                        act + AOFF_ED4, 262144, 512,  w + OFF_Vt3, 2097152, 512, 512,
                        t3, 4096, ed3, OUT_LD, -1.f, eg3, OUT_LD, -1.f, 1.f);
        launch_batch(pa, 3, 4096);

        // ---- LIF update (+ ed1, eg3, x splits) ----
        lif_k<<<(3 * S_LAYER + 255) / 256, 256>>>(out);

        // ---- Phase B: error signals — ONE launch, z = 4 ----
        TG pbt[4];
        // eg1 = 0.5*x1 - 0.5*(x2 @ W1^T)
        pbt[0] = make_tg(act + AOFF_X2, 2097152, 4096, w + OFF_W1d, 16777216, 4096, 4096,
                         nullptr, 0, 0, nullptr, 0, 0, 0,
                         eg1, OUT_LD, x1, 4096, 0.5f, nullptr, 0, 0.f, -0.5f,
                         act + AOFF_EG1, 2097152, 4096);
        // ed2 = 0.5*x2 - 0.5*(x1 @ V1^T)
        pbt[1] = make_tg(act + AOFF_X1, 2097152, 4096, w + OFF_V1d, 16777216, 4096, 4096,
                         nullptr, 0, 0, nullptr, 0, 0, 0,
                         ed2, OUT_LD, x2, 4096, 0.5f, nullptr, 0, 0.f, -0.5f,
                         act + AOFF_ED2, 2097152, 4096);
        // eg2 = 0.5*x2 - 0.5*(x3 @ W2^T)
        pbt[2] = make_tg(act + AOFF_X3, 2097152, 4096, w + OFF_W2d, 16777216, 4096, 4096,
                         nullptr, 0, 0, nullptr, 0, 0, 0,
                         eg2, OUT_LD, x2, 4096, 0.5f, nullptr, 0, 0.f, -0.5f,
                         act + AOFF_EG2, 2097152, 4096);
        // ed3 = 0.5*x3 - 0.5*(x2 @ V2^T)
        pbt[3] = make_tg(act + AOFF_X2, 2097152, 4096, w + OFF_V2d, 16777216, 4096, 4096,
                         nullptr, 0, 0, nullptr, 0, 0, 0,
                         ed3, OUT_LD, x3, 4096, 0.5f, nullptr, 0, 0.f, -0.5f,
                         act + AOFF_ED3, 2097152, 4096);
        launch_batch(pbt, 4, 4096);

        // eg0: split-K 4x of x1 @ W0^T (N=1024, K=4096) -> partials + reduce
        {
            TG g = make_tg(act + AOFF_X1, 2097152, 4096, w + OFF_W0d, 4194304, 4096, 4096,
                           nullptr, 0, 0, nullptr, 0, 0, 0,
                           pA, 1024, nullptr, 0, 0.f, nullptr, 0, 0.f, 1.f,
                           nullptr, 0, 0, /*kc=*/1024, /*czstride=*/524288);
            launch_splitk(g, 4, 1024);
        }
        reduce_k<<<(512 * 1024 + 255) / 256, 256>>>(pA, 4, xd, 1024, out, 0, 1024,
                                                    act + AOFF_EG0, 524288);

        // ed4: split-K 8x of x3 @ V3^T (N=512, K=4096) -> partials + reduce
        {
            TG g = make_tg(act + AOFF_X3, 2097152, 4096, w + OFF_V3d, 2097152, 4096, 4096,
                           nullptr, 0, 0, nullptr, 0, 0, 0,
                           pB, 512, nullptr, 0, 0.f, nullptr, 0, 0.f, 1.f,
                           nullptr, 0, 0, /*kc=*/512, /*czstride=*/262144);
            launch_splitk(g, 8, 512);
        }
        reduce_k<<<(512 * 512 + 255) / 256, 256>>>(pB, 8, yt, 512, out, 25600, 512,
                                                   act + AOFF_ED4, 262144);
    }
}

// round 16
// speedup vs baseline: 1.0721x; 1.0721x over previous
#include <cuda_runtime.h>
#include <cuda_bf16.h>
#include <cstdint>

// ---------------------------------------------------------------------------
// bPC SNN, 25 steps. Round 16: HMMA bf16x3 6-product GEMM.
//   - Numerics identical to R13/R15 (proven rel_err 5.22e-6).
//   - NEW: analytic step 1 (all-zero carry -> closed-form errors) in one
//     elementwise kernel; generic loop runs 24 iterations.
//   - NEW: Phase-B mega-batch: one launch, 16 z-entries (4 main GEMMs +
//     4 eg0 split-K chunks + 8 ed4 chunks, pointers pre-offset, Nlim
//     early-exit). Per-step GEMM launches: 7 -> 2.
//   - NEW: B-resident / A-streamed 6-product inner loop (lower reg pressure).
//   - NEW: setup ordered so process-launch index 3 is gemm_mma (observed
//     ncu capture lands on index 3).
// ---------------------------------------------------------------------------

#define S_LAYER (512 * 4096)
#define OUT_LD  26112

typedef __nv_bfloat16 bf16;

// ---- device storage -------------------------------------------------------
__device__ float g_state[9 * S_LAYER];          // j1..3 | v1..3 | x1..3
__device__ float g_tin[3 * S_LAYER];            // injected currents
__device__ float g_c1h[S_LAYER];                // 0.5 * x_data @ V0^T
__device__ float g_c2h[S_LAYER];                // 0.5 * y_target @ W3^T
__device__ bf16  g_w[459276288];                // weight splits (direct+T), x3
__device__ bf16  g_act[46399488];               // activation splits, x3
__device__ bf16  g_io[2359296];                 // xd/yt splits, x3
__device__ float g_pA[4 * 512 * 1024];          // eg0 split-K partials
__device__ float g_pB[8 * 512 * 512];           // ed4 split-K partials

// ---- weight slab offsets (elements); each slab = [3][N][K] ----------------
#define OFF_W0d   0L            // [1024,4096]
#define OFF_V0d   12582912L     // [4096,1024]
#define OFF_W1d   25165824L     // [4096,4096]
#define OFF_V1d   75497472L
#define OFF_W2d   125829120L
#define OFF_V2d   176160768L
#define OFF_W3d   226492416L    // [4096,512]
#define OFF_V3d   232783872L    // [512,4096]
#define OFF_Wt0   239075328L    // [4096,1024]
#define OFF_Wt1   251658240L    // [4096,4096]
#define OFF_Vt1   301989888L
#define OFF_Wt2   352321536L
#define OFF_Vt2   402653184L
#define OFF_Vt3   452984832L    // [4096,512]

// activation slab offsets; each slab = [3][512][K]
#define AOFF_EG0  0L            // [512,1024]
#define AOFF_EG1  1572864L      // [512,4096]
#define AOFF_ED2  7864320L
#define AOFF_EG2  14155776L
#define AOFF_ED3  20447232L
#define AOFF_ED4  26738688L     // [512,512]
#define AOFF_X1   27525120L     // [512,4096]
#define AOFF_X2   33816576L
#define AOFF_X3   40108032L

// ---------------------------------------------------------------------------
__device__ __forceinline__ uint32_t smem_u32(const void* p) {
    uint32_t a;
    asm("{ .reg .u64 t; cvta.to.shared.u64 t, %1; cvt.u32.u64 %0, t; }"
        : "=r"(a) : "l"(p));
    return a;
}
#define CP16(dst, src) \
    asm volatile("cp.async.cg.shared.global [%0], [%1], 16;" \
                 :: "r"(dst), "l"(src) : "memory")
#define CP_COMMIT() asm volatile("cp.async.commit_group;" ::: "memory")
#define CP_WAIT1()  asm volatile("cp.async.wait_group 1;" ::: "memory")
#define CP_WAIT0()  asm volatile("cp.async.wait_group 0;" ::: "memory")

__device__ __forceinline__ void ldsm_x4(uint32_t (&r)[4], uint32_t addr) {
    asm volatile("ldmatrix.sync.aligned.m8n8.x4.shared.b16 {%0,%1,%2,%3}, [%4];"
                 : "=r"(r[0]), "=r"(r[1]), "=r"(r[2]), "=r"(r[3]) : "r"(addr));
}
__device__ __forceinline__ void mma_bf16(float (&c)[4], const uint32_t (&a)[4],
                                         uint32_t b0, uint32_t b1) {
    asm volatile(
        "mma.sync.aligned.m16n8k16.row.col.f32.bf16.bf16.f32 "
        "{%0,%1,%2,%3}, {%4,%5,%6,%7}, {%8,%9}, {%0,%1,%2,%3};"
        : "+f"(c[0]), "+f"(c[1]), "+f"(c[2]), "+f"(c[3])
        : "r"(a[0]), "r"(a[1]), "r"(a[2]), "r"(a[3]), "r"(b0), "r"(b1));
}

// ---------------------------------------------------------------------------
// GEMM: C[512,Nlim] = alpha * sum6( A_s @ B_s^T ) + g0*aux0 + g1*aux1
//       (+ optional bf16x3 split emission of C)
// A slabs: [3][512][*] bf16, k-contiguous rows. B slabs: [3][N][*] bf16.
// grid.z indexes the TG table; CTAs with bn >= Nlim exit (mixed-N batching).
// ---------------------------------------------------------------------------
struct TG {
    const bf16 *A1, *B1, *A2, *B2;
    long sA1, sB1, sA2, sB2;        // per-split slab strides
    int  lda1, ldb1, lda2, ldb2;    // row strides (elements)
    int  K1, K2;
    float* C; int ldc;
    const float* aux0; int ld0; float g0;
    const float* aux1; int ld1; float g1;
    float alpha;
    bf16* so; long sso; int ldso;   // optional split output [3][512][N]
    int  Nlim;
};
struct TGB { TG g[16]; };

#define TILE_B   10240            // 128 rows x 80B (32 bf16 + 8B pad)
#define STAGE_B  (6 * TILE_B)     // A0,A1,A2,B0,B1,B2
#define SMEM_MM  (3 * STAGE_B)    // 3-stage pipeline = 184320 B

__global__ __launch_bounds__(256, 1) void gemm_mma(TGB pb) {
    extern __shared__ char smem[];
    const TG& p = pb.g[blockIdx.z];
    const int bn = blockIdx.x * 128;
    if (bn >= p.Nlim) return;           // mixed-N batching early exit
    const uint32_t sb = smem_u32(smem);
    const int tid  = threadIdx.x;
    const int wid  = tid >> 5;
    const int lane = tid & 31;
    const int bm   = blockIdx.y * 128;
    const int wm   = (wid & 1) * 64;
    const int wn   = (wid >> 1) * 32;

    const int nk1 = p.K1 >> 5;
    const int nk  = (p.K1 + p.K2) >> 5;
    float* C = p.C;

    float acc[4][4][4];
#pragma unroll
    for (int i = 0; i < 4; i++)
#pragma unroll
        for (int j = 0; j < 4; j++)
#pragma unroll
            for (int q = 0; q < 4; q++) acc[i][j][q] = 0.0f;

    auto load_chunk = [&](int c, int s) {
        const bool seg2 = (c >= nk1);
        const bf16* Ab = seg2 ? p.A2 : p.A1;
        const bf16* Bb = seg2 ? p.B2 : p.B1;
        const long  sA = seg2 ? p.sA2 : p.sA1;
        const long  sB = seg2 ? p.sB2 : p.sB1;
        const int   la = seg2 ? p.lda2 : p.lda1;
        const int   lb = seg2 ? p.ldb2 : p.ldb1;
        const long  kcoff = (long)(seg2 ? c - nk1 : c) * 32;
        const uint32_t base = sb + s * STAGE_B;
#pragma unroll
        for (int sp = 0; sp < 3; sp++) {
            const bf16* ga = Ab + sp * sA + kcoff;
            const bf16* gb = Bb + sp * sB + kcoff;
#pragma unroll
            for (int i = 0; i < 2; i++) {
                const int id  = tid + i * 256;
                const int row = id >> 2;
                const int seg = (id & 3) * 16;
                CP16(base + sp * TILE_B + row * 80 + seg,
                     (const char*)(ga + (long)(bm + row) * la) + seg);
                CP16(base + (3 + sp) * TILE_B + row * 80 + seg,
                     (const char*)(gb + (long)(bn + row) * lb) + seg);
            }
        }
        CP_COMMIT();
    };

    load_chunk(0, 0);
    load_chunk(1, 1);

#define LDA(F, abase, kk)                                                      \
    _Pragma("unroll")                                                          \
    for (int i = 0; i < 4; i++)                                                \
        ldsm_x4(F[i], (abase) + (uint32_t)(wm + 16 * i + (lane & 15)) * 80     \
                        + (kk) * 32 + (lane >> 4) * 16);
#define LDB(F, bbase, kk)                                                      \
    _Pragma("unroll")                                                          \
    for (int h = 0; h < 2; h++)                                                \
        ldsm_x4(F[h], (bbase) + (uint32_t)(wn + 16 * h + 8 * ((lane >> 4) & 1) \
                        + (lane & 7)) * 80 + (kk) * 32 + ((lane >> 3) & 1) * 16);
#define MMAS(AF, BF)                                                           \
    _Pragma("unroll")                                                          \
    for (int i = 0; i < 4; i++)                                                \
        _Pragma("unroll")                                                      \
        for (int j = 0; j < 4; j++)                                            \
            mma_bf16(acc[i][j], AF[i], BF[j >> 1][(j & 1) * 2],                \
                     BF[j >> 1][(j & 1) * 2 + 1]);

    for (int c = 0; c < nk; c++) {
        if (c + 1 < nk) CP_WAIT1(); else CP_WAIT0();
        __syncthreads();
        if (c + 2 < nk) load_chunk(c + 2, (c + 2) % 3);

        const uint32_t base = sb + (c % 3) * STAGE_B;
        const uint32_t a0 = base,              a1 = base + TILE_B,     a2 = base + 2 * TILE_B;
        const uint32_t b0 = base + 3 * TILE_B, b1 = base + 4 * TILE_B, b2 = base + 5 * TILE_B;
#pragma unroll
        for (int kk = 0; kk < 2; kk++) {
            // B-resident, A-streamed 6-product schedule (lower reg pressure):
            uint32_t B0[2][4], B1r[2][4], B2r[2][4], A[4][4];
            LDB(B0, b0, kk); LDB(B1r, b1, kk); LDB(B2r, b2, kk);
            LDA(A, a0, kk);                     // Ah
            MMAS(A, B0);                        // hi * hi
            MMAS(A, B1r);                       // hi * mid
            MMAS(A, B2r);                       // hi * lo
            LDA(A, a1, kk);                     // Am
            MMAS(A, B0);                        // mid * hi
            MMAS(A, B1r);                       // mid * mid
            LDA(A, a2, kk);                     // Al
            MMAS(A, B0);                        // lo * hi
        }
        // no trailing sync: stage (c+2)%3 was last read at chunk c-1, which
        // every warp finished before passing this chunk's top barrier.
    }
#undef LDA
#undef LDB
#undef MMAS

    // ---- epilogue ---------------------------------------------------------
    const int r0    = lane >> 2;
    const int cpair = (lane & 3) * 2;
#pragma unroll
    for (int i = 0; i < 4; i++) {
        const long gr = bm + wm + 16 * i + r0;
#pragma unroll
        for (int j = 0; j < 4; j++) {
            const int gc = bn + wn + 8 * j + cpair;
            float v[4];
            v[0] = p.alpha * acc[i][j][0];
            v[1] = p.alpha * acc[i][j][1];
            v[2] = p.alpha * acc[i][j][2];
            v[3] = p.alpha * acc[i][j][3];
            if (p.aux0) {
                const float2 u0 = *(const float2*)(p.aux0 + gr * p.ld0 + gc);
                const float2 u1 = *(const float2*)(p.aux0 + (gr + 8) * p.ld0 + gc);
                v[0] += p.g0 * u0.x; v[1] += p.g0 * u0.y;
                v[2] += p.g0 * u1.x; v[3] += p.g0 * u1.y;
            }
            if (p.aux1) {
                const float2 u0 = *(const float2*)(p.aux1 + gr * p.ld1 + gc);
                const float2 u1 = *(const float2*)(p.aux1 + (gr + 8) * p.ld1 + gc);
                v[0] += p.g1 * u0.x; v[1] += p.g1 * u0.y;
                v[2] += p.g1 * u1.x; v[3] += p.g1 * u1.y;
            }
            *(float2*)(C + gr * p.ldc + gc)       = make_float2(v[0], v[1]);
            *(float2*)(C + (gr + 8) * p.ldc + gc) = make_float2(v[2], v[3]);
            if (p.so) {                         // fused bf16x3 split emission
                bf16 h[4], m[4], l[4];
#pragma unroll
                for (int q = 0; q < 4; q++) {
                    h[q] = __float2bfloat16(v[q]);
                    const float r1 = v[q] - __bfloat162float(h[q]);
                    m[q] = __float2bfloat16(r1);
                    l[q] = __float2bfloat16(r1 - __bfloat162float(m[q]));
                }
                __nv_bfloat162 P;
                P.x = h[0]; P.y = h[1];
                *(__nv_bfloat162*)(p.so + gr * p.ldso + gc) = P;
                P.x = h[2]; P.y = h[3];
                *(__nv_bfloat162*)(p.so + (gr + 8) * p.ldso + gc) = P;
                P.x = m[0]; P.y = m[1];
                *(__nv_bfloat162*)(p.so + p.sso + gr * p.ldso + gc) = P;
                P.x = m[2]; P.y = m[3];
                *(__nv_bfloat162*)(p.so + p.sso + (gr + 8) * p.ldso + gc) = P;
                P.x = l[0]; P.y = l[1];
                *(__nv_bfloat162*)(p.so + 2 * p.sso + gr * p.ldso + gc) = P;
                P.x = l[2]; P.y = l[3];
                *(__nv_bfloat162*)(p.so + 2 * p.sso + (gr + 8) * p.ldso + gc) = P;
            }
        }
    }
}

// ---------------------------------------------------------------------------
// Split-K reduce: e = 0.5*ref - 0.5*sum_z P[z]; write float + bf16x3 splits
// ---------------------------------------------------------------------------
__global__ void reduce_k(const float* __restrict__ P, int nsplit,
                         const float* __restrict__ ref, int ldref,
                         float* __restrict__ out, int outoff, int N,
                         bf16* __restrict__ so, long sso) {
    const int idx = blockIdx.x * blockDim.x + threadIdx.x;
    if (idx >= 512 * N) return;
    const int  b    = idx / N;
    const int  f    = idx - b * N;
    const long slab = (long)512 * N;
    float s = 0.0f;
    for (int z = 0; z < nsplit; ++z) s += P[z * slab + idx];
    const float e = 0.5f * ref[(long)b * ldref + f] - 0.5f * s;
    out[(long)b * OUT_LD + outoff + f] = e;
    const bf16 h = __float2bfloat16(e);
    const float r1 = e - __bfloat162float(h);
    const bf16 m = __float2bfloat16(r1);
    so[idx]           = h;
    so[sso + idx]     = m;
    so[2 * sso + idx] = __float2bfloat16(r1 - __bfloat162float(m));
}

// ---------------------------------------------------------------------------
// splitters (weights / inputs, once per launch)
// ---------------------------------------------------------------------------
__global__ void split_k(const float* __restrict__ in, int ld, int rows, int cols,
                        bf16* __restrict__ out) {
    const long n = (long)rows * cols;
    const long idx = (long)blockIdx.x * blockDim.x + threadIdx.x;
    if (idx >= n) return;
    const int r = (int)(idx / cols), c = (int)(idx - (long)r * cols);
    const float a = in[(long)r * ld + c];
    const bf16 h = __float2bfloat16(a);
    const float f1 = a - __bfloat162float(h);
    const bf16 m = __float2bfloat16(f1);
    out[idx]         = h;
    out[n + idx]     = m;
    out[2 * n + idx] = __float2bfloat16(f1 - __bfloat162float(m));
}
__global__ void splitT_k(const float* __restrict__ in, int ldin, int K, int N,
                         bf16* __restrict__ out) {
    const long n = (long)N * K;
    const long idx = (long)blockIdx.x * blockDim.x + threadIdx.x;
    if (idx >= n) return;
    const int nn = (int)(idx / K), k = (int)(idx - (long)nn * K);
    const float a = in[(long)k * ldin + nn];
    const bf16 h = __float2bfloat16(a);
    const float f1 = a - __bfloat162float(h);
    const bf16 m = __float2bfloat16(f1);
    out[idx]         = h;
    out[n + idx]     = m;
    out[2 * n + idx] = __float2bfloat16(f1 - __bfloat162float(m));
}

// ---------------------------------------------------------------------------
// Analytic step 1 (carry all-zero):
//   eg0 = 0.5*xd ; ed1 = -c1h ; eg3 = -c2h ; ed4 = 0.5*yt ; rest stay 0.
// Also emits EG0/ED4 bf16x3 splits (consumed by step-2 Phase A).
// ---------------------------------------------------------------------------
__global__ void init_err_k(float* dout, const float* __restrict__ xd,
                           const float* __restrict__ yt) {
    const long N0 = 512L * 1024;         // eg0
    const long N1 = 512L * 4096;         // ed1 / eg3 each
    const long total = N0 + 2 * N1 + 512L * 512;
    const long idx = (long)blockIdx.x * blockDim.x + threadIdx.x;
    if (idx >= total) return;
    if (idx < N0) {                      // eg0 = 0.5*xd  (+ splits)
        const int b = (int)(idx >> 10), f = (int)(idx & 1023);
        const float e = 0.5f * xd[idx];
        dout[(long)b * OUT_LD + f] = e;
        const bf16 h = __float2bfloat16(e);
        const float r1 = e - __bfloat162float(h);
        const bf16 m = __float2bfloat16(r1);
        g_act[AOFF_EG0 + idx]           = h;
        g_act[AOFF_EG0 + 524288 + idx]  = m;
        g_act[AOFF_EG0 + 1048576 + idx] = __float2bfloat16(r1 - __bfloat162float(m));
    } else if (idx < N0 + N1) {          // ed1 = -c1h
        const long r = idx - N0;
        const int b = (int)(r >> 12), f = (int)(r & 4095);
        dout[(long)b * OUT_LD + 13312 + f] = -g_c1h[r];
    } else if (idx < N0 + 2 * N1) {      // eg3 = -c2h
        const long r = idx - N0 - N1;
        const int b = (int)(r >> 12), f = (int)(r & 4095);
        dout[(long)b * OUT_LD + 9216 + f] = -g_c2h[r];
    } else {                             // ed4 = 0.5*yt  (+ splits)
        const long r = idx - N0 - 2 * N1;
        const int b = (int)(r >> 9), f = (int)(r & 511);
        const float e = 0.5f * yt[r];
        dout[(long)b * OUT_LD + 25600 + f] = e;
        const bf16 h = __float2bfloat16(e);
        const float r1 = e - __bfloat162float(h);
        const bf16 m = __float2bfloat16(r1);
        g_act[AOFF_ED4 + r]          = h;
        g_act[AOFF_ED4 + 262144 + r] = m;
        g_act[AOFF_ED4 + 524288 + r] = __float2bfloat16(r1 - __bfloat162float(m));
    }
}

// ---------------------------------------------------------------------------
// LIF update; emits ed1/eg3 (float) and x1..3 bf16x3 splits
// ---------------------------------------------------------------------------
__global__ void lif_k(float* dout) {
    const long idx = (long)blockIdx.x * blockDim.x + threadIdx.x;
    if (idx >= 3L * S_LAYER) return;
    const int L = (int)(idx / S_LAYER);
    const int r = (int)(idx - (long)L * S_LAYER);

    const float tin = g_tin[idx];
    float j = g_state[idx];
    float v = g_state[3L * S_LAYER + idx];
    float x = g_state[6L * S_LAYER + idx];

    j = j + 0.25f * (tin - j);
    v = v + 0.05f * (j - v);
    const float spk = (v > 1.0f) ? 1.0f : 0.0f;
    v = v * (1.0f - spk);
    x = x * (1.0f - 0.025f) + spk;

    g_state[idx] = j;
    g_state[3L * S_LAYER + idx] = v;
    g_state[6L * S_LAYER + idx] = x;

    const long xb = AOFF_X1 + (long)L * 6291456L + r;
    const bf16 h = __float2bfloat16(x);
    const float f1 = x - __bfloat162float(h);
    const bf16 m = __float2bfloat16(f1);
    g_act[xb]            = h;
    g_act[xb + 2097152L] = m;
    g_act[xb + 4194304L] = __float2bfloat16(f1 - __bfloat162float(m));

    if (L == 0) {                         // ed1 = 0.5*x1 - c1h
        const int b = r >> 12, f = r & 4095;
        dout[(long)b * OUT_LD + 13312 + f] = 0.5f * x - g_c1h[r];
    } else if (L == 2) {                  // eg3 = 0.5*x3 - c2h
        const int b = r >> 12, f = r & 4095;
        dout[(long)b * OUT_LD + 9216 + f] = 0.5f * x - g_c2h[r];
    }
}

__global__ void zero_k(float* dout) {
    const long n1 = 9L * S_LAYER;
    const long n2 = 27525120L;            // act EG0..ED4 region
    const long n3 = 512L * OUT_LD;
    for (long i = (long)blockIdx.x * blockDim.x + threadIdx.x; i < n1 + n2 + n3;
         i += (long)gridDim.x * blockDim.x) {
        if (i < n1)            g_state[i] = 0.0f;
        else if (i < n1 + n2)  g_act[i - n1] = __float2bfloat16(0.0f);
        else                   dout[i - n1 - n2] = 0.0f;
    }
}

// ---------------------------------------------------------------------------
static TG make_tg(const bf16* A1, long sA1, int lda1,
                  const bf16* B1, long sB1, int ldb1, int K1,
                  const bf16* A2, long sA2, int lda2,
                  const bf16* B2, long sB2, int ldb2, int K2,
                  float* C, int ldc,
                  const float* a0, int l0, float g0,
                  const float* a1, int l1, float g1,
                  float alpha, int Nlim,
                  bf16* so = nullptr, long sso = 0, int ldso = 0) {
    TG p;
    p.A1 = A1; p.sA1 = sA1; p.lda1 = lda1;
    p.B1 = B1; p.sB1 = sB1; p.ldb1 = ldb1; p.K1 = K1;
    p.A2 = A2 ? A2 : A1; p.sA2 = sA2; p.lda2 = lda2;
    p.B2 = B2 ? B2 : B1; p.sB2 = sB2; p.ldb2 = ldb2; p.K2 = K2;
    p.C = C; p.ldc = ldc;
    p.aux0 = a0; p.ld0 = l0; p.g0 = g0;
    p.aux1 = a1; p.ld1 = l1; p.g1 = g1;
    p.alpha = alpha;
    p.so = so; p.sso = sso; p.ldso = ldso;
    p.Nlim = Nlim;
    return p;
}

static void launch_batch(const TG* tg, int nz, int maxN) {
    TGB pb{};
    for (int z = 0; z < nz; z++) pb.g[z] = tg[z];
    dim3 grid(maxN / 128, 4, nz);
    gemm_mma<<<grid, 256, SMEM_MM>>>(pb);
}

extern "C" void kernel_launch(void* const* d_in, const int* in_sizes, int n_in,
                              void* d_out, int out_size) {
    (void)in_sizes; (void)n_in; (void)out_size;
    const float* xd = (const float*)d_in[0];   // (512, 1024)
    const float* yt = (const float*)d_in[1];   // (512, 512)
    const float* W0 = (const float*)d_in[2];
    const float* V0 = (const float*)d_in[3];
    const float* W1 = (const float*)d_in[4];
    const float* V1 = (const float*)d_in[5];
    const float* W2 = (const float*)d_in[6];
    const float* V2 = (const float*)d_in[7];
    const float* W3 = (const float*)d_in[8];
    const float* V3 = (const float*)d_in[9];
    float* out = (float*)d_out;

    cudaFuncSetAttribute(gemm_mma, cudaFuncAttributeMaxDynamicSharedMemorySize, SMEM_MM);

    float *st, *tin, *c1h, *c2h, *pA, *pB; bf16 *w, *act, *io;
    cudaGetSymbolAddress((void**)&st,  g_state);
    cudaGetSymbolAddress((void**)&tin, g_tin);
    cudaGetSymbolAddress((void**)&c1h, g_c1h);
    cudaGetSymbolAddress((void**)&c2h, g_c2h);
    cudaGetSymbolAddress((void**)&w,   g_w);
    cudaGetSymbolAddress((void**)&act, g_act);
    cudaGetSymbolAddress((void**)&io,  g_io);
    cudaGetSymbolAddress((void**)&pA,  g_pA);
    cudaGetSymbolAddress((void**)&pB,  g_pB);

    float* x1 = st + 6L * S_LAYER;
    float* x2 = st + 7L * S_LAYER;
    float* x3 = st + 8L * S_LAYER;
    float* t1 = tin;
    float* t2 = tin + S_LAYER;
    float* t3 = tin + 2L * S_LAYER;

    float* eg1 = out + 1024;
    float* eg2 = out + 5120;
    float* eg3 = out + 9216;     // written by lif_k / init_err_k
    float* ed1 = out + 13312;    // written by lif_k / init_err_k
    float* ed2 = out + 17408;
    float* ed3 = out + 21504;

    // ---- setup; process-launch index 3 is gemm_mma (ncu lands there) ------
    zero_k<<<2048, 256>>>(out);                                                     // 0
    split_k<<<(512 * 1024 + 255) / 256, 256>>>(xd, 1024, 512, 1024, io);            // 1
    split_k<<<(4096 * 1024 + 255) / 256, 256>>>(V0, 1024, 4096, 1024, w + OFF_V0d); // 2
    {   // 3: c1h = 0.5 * xd @ V0^T   (N=4096, K=1024) — profiled launch
        TG g = make_tg(io, 524288, 1024, w + OFF_V0d, 4194304, 1024, 1024,
                       nullptr, 0, 0, nullptr, 0, 0, 0,
                       c1h, 4096, nullptr, 0, 0.f, nullptr, 0, 0.f, 0.5f, 4096);
        launch_batch(&g, 1, 4096);
    }
    split_k<<<(512 * 512  + 255) / 256, 256>>>(yt, 512,  512, 512,  io + 1572864);  // 4
    split_k<<<(4096 * 512  + 255) / 256, 256>>>(W3, 512,  4096, 512,  w + OFF_W3d); // 5
    {   // 6: c2h = 0.5 * yt @ W3^T   (N=4096, K=512)
        TG g = make_tg(io + 1572864, 262144, 512, w + OFF_W3d, 2097152, 512, 512,
                       nullptr, 0, 0, nullptr, 0, 0, 0,
                       c2h, 4096, nullptr, 0, 0.f, nullptr, 0, 0.f, 0.5f, 4096);
        launch_batch(&g, 1, 4096);
    }
    // 7: analytic step 1 (carry all-zero -> closed-form errors)
    init_err_k<<<(int)((512L * 1024 + 2 * 512L * 4096 + 512L * 512 + 255) / 256), 256>>>(out, xd, yt);

    split_k<<<(1024 * 4096 + 255) / 256, 256>>>(W0, 4096, 1024, 4096, w + OFF_W0d);
    split_k<<<(4096 * 4096 + 255) / 256, 256>>>(W1, 4096, 4096, 4096, w + OFF_W1d);
    split_k<<<(4096 * 4096 + 255) / 256, 256>>>(V1, 4096, 4096, 4096, w + OFF_V1d);
    split_k<<<(4096 * 4096 + 255) / 256, 256>>>(W2, 4096, 4096, 4096, w + OFF_W2d);
    split_k<<<(4096 * 4096 + 255) / 256, 256>>>(V2, 4096, 4096, 4096, w + OFF_V2d);
    split_k<<<(512  * 4096 + 255) / 256, 256>>>(V3, 4096, 512,  4096, w + OFF_V3d);
    splitT_k<<<(4096 * 1024 + 255) / 256, 256>>>(W0, 4096, 1024, 4096, w + OFF_Wt0);
    splitT_k<<<(4096 * 4096 + 255) / 256, 256>>>(W1, 4096, 4096, 4096, w + OFF_Wt1);
    splitT_k<<<(4096 * 4096 + 255) / 256, 256>>>(V1, 4096, 4096, 4096, w + OFF_Vt1);
    splitT_k<<<(4096 * 4096 + 255) / 256, 256>>>(W2, 4096, 4096, 4096, w + OFF_Wt2);
    splitT_k<<<(4096 * 4096 + 255) / 256, 256>>>(V2, 4096, 4096, 4096, w + OFF_Vt2);
    splitT_k<<<(4096 * 512  + 255) / 256, 256>>>(V3, 4096, 512,  4096, w + OFF_Vt3);

    // ---- steps 2..25 (step 1 done analytically) ----
    const int NUM_STEPS = 25;
    for (int t = 1; t < NUM_STEPS; t++) {
        // ---- Phase A: injected currents — ONE launch, z = 3 ----
        TG pa[3];
        pa[0] = make_tg(act + AOFF_EG0, 524288, 1024, w + OFF_Wt0, 4194304, 1024, 1024,
                        act + AOFF_ED2, 2097152, 4096, w + OFF_Vt1, 16777216, 4096, 4096,
                        t1, 4096, ed1, OUT_LD, -1.f, eg1, OUT_LD, -1.f, 1.f, 4096);
        pa[1] = make_tg(act + AOFF_EG1, 2097152, 4096, w + OFF_Wt1, 16777216, 4096, 4096,
                        act + AOFF_ED3, 2097152, 4096, w + OFF_Vt2, 16777216, 4096, 4096,
                        t2, 4096, ed2, OUT_LD, -1.f, eg2, OUT_LD, -1.f, 1.f, 4096);
        pa[2] = make_tg(act + AOFF_EG2, 2097152, 4096, w + OFF_Wt2, 16777216, 4096, 4096,
                        act + AOFF_ED4, 262144, 512,  w + OFF_Vt3, 2097152, 512, 512,
                        t3, 4096, ed3, OUT_LD, -1.f, eg3, OUT_LD, -1.f, 1.f, 4096);
        launch_batch(pa, 3, 4096);

        // ---- LIF update (+ ed1, eg3, x splits) ----
        lif_k<<<(3 * S_LAYER + 255) / 256, 256>>>(out);

        // ---- Phase B mega-batch: 4 mains + 4 eg0 chunks + 8 ed4 chunks ----
        TG pbt[16];
        pbt[0] = make_tg(act + AOFF_X2, 2097152, 4096, w + OFF_W1d, 16777216, 4096, 4096,
                         nullptr, 0, 0, nullptr, 0, 0, 0,
                         eg1, OUT_LD, x1, 4096, 0.5f, nullptr, 0, 0.f, -0.5f, 4096,
                         act + AOFF_EG1, 2097152, 4096);
        pbt[1] = make_tg(act + AOFF_X1, 2097152, 4096, w + OFF_V1d, 16777216, 4096, 4096,
                         nullptr, 0, 0, nullptr, 0, 0, 0,
                         ed2, OUT_LD, x2, 4096, 0.5f, nullptr, 0, 0.f, -0.5f, 4096,
                         act + AOFF_ED2, 2097152, 4096);
        pbt[2] = make_tg(act + AOFF_X3, 2097152, 4096, w + OFF_W2d, 16777216, 4096, 4096,
                         nullptr, 0, 0, nullptr, 0, 0, 0,
                         eg2, OUT_LD, x2, 4096, 0.5f, nullptr, 0, 0.f, -0.5f, 4096,
                         act + AOFF_EG2, 2097152, 4096);
        pbt[3] = make_tg(act + AOFF_X2, 2097152, 4096, w + OFF_V2d, 16777216, 4096, 4096,
                         nullptr, 0, 0, nullptr, 0, 0, 0,
                         ed3, OUT_LD, x3, 4096, 0.5f, nullptr, 0, 0.f, -0.5f, 4096,
                         act + AOFF_ED3, 2097152, 4096);
        for (int c = 0; c < 4; c++)          // eg0 split-K chunks (K=1024 each)
            pbt[4 + c] = make_tg(act + AOFF_X1 + c * 1024, 2097152, 4096,
                                 w + OFF_W0d + c * 1024, 4194304, 4096, 1024,
                                 nullptr, 0, 0, nullptr, 0, 0, 0,
                                 pA + (long)c * 524288, 1024,
                                 nullptr, 0, 0.f, nullptr, 0, 0.f, 1.f, 1024);
        for (int c = 0; c < 8; c++)          // ed4 split-K chunks (K=512 each)
            pbt[8 + c] = make_tg(act + AOFF_X3 + c * 512, 2097152, 4096,
                                 w + OFF_V3d + c * 512, 2097152, 4096, 512,
                                 nullptr, 0, 0, nullptr, 0, 0, 0,
                                 pB + (long)c * 262144, 512,
                                 nullptr, 0, 0.f, nullptr, 0, 0.f, 1.f, 512);
        launch_batch(pbt, 16, 4096);

        reduce_k<<<(512 * 1024 + 255) / 256, 256>>>(pA, 4, xd, 1024, out, 0, 1024,
                                                    act + AOFF_EG0, 524288);
        reduce_k<<<(512 * 512 + 255) / 256, 256>>>(pB, 8, yt, 512, out, 25600, 512,
                                                   act + AOFF_ED4, 262144);
    }
}

// round 17
// speedup vs baseline: 1.1025x; 1.0284x over previous
#include <cuda_runtime.h>
#include <cuda_bf16.h>
#include <cstdint>

// ---------------------------------------------------------------------------
// bPC SNN, 25 steps. Round 17: HMMA bf16x3 6-product GEMM, 16-warp CTA.
//   - R16 ncu: tensor=48.9%, occ=12.5%, issue=13.9%, DRAM=4.2% -> mainloop is
//     latency-bound at 2 warps/SMSP, NOT HMMA-throughput bound.
//   - NEW: 512 threads / 16 warps per CTA (4 warps/SMSP), warp tile 32x32
//     (4x4 warp grid). Per-element accumulation order is bit-identical to
//     R16 (same product/k sequence), so rel_err must stay 5.2168e-6.
//   - Kept: bf16x3 / 6 products, depth-3 single-sync cp.async pipeline,
//     fused split emission, analytic step 1, Phase-B mega-batch (z=16),
//     80B-pitch smem.
// ---------------------------------------------------------------------------

#define S_LAYER (512 * 4096)
#define OUT_LD  26112

typedef __nv_bfloat16 bf16;

// ---- device storage -------------------------------------------------------
__device__ float g_state[9 * S_LAYER];          // j1..3 | v1..3 | x1..3
__device__ float g_tin[3 * S_LAYER];            // injected currents
__device__ float g_c1h[S_LAYER];                // 0.5 * x_data @ V0^T
__device__ float g_c2h[S_LAYER];                // 0.5 * y_target @ W3^T
__device__ bf16  g_w[459276288];                // weight splits (direct+T), x3
__device__ bf16  g_act[46399488];               // activation splits, x3
__device__ bf16  g_io[2359296];                 // xd/yt splits, x3
__device__ float g_pA[4 * 512 * 1024];          // eg0 split-K partials
__device__ float g_pB[8 * 512 * 512];           // ed4 split-K partials

// ---- weight slab offsets (elements); each slab = [3][N][K] ----------------
#define OFF_W0d   0L            // [1024,4096]
#define OFF_V0d   12582912L     // [4096,1024]
#define OFF_W1d   25165824L     // [4096,4096]
#define OFF_V1d   75497472L
#define OFF_W2d   125829120L
#define OFF_V2d   176160768L
#define OFF_W3d   226492416L    // [4096,512]
#define OFF_V3d   232783872L    // [512,4096]
#define OFF_Wt0   239075328L    // [4096,1024]
#define OFF_Wt1   251658240L    // [4096,4096]
#define OFF_Vt1   301989888L
#define OFF_Wt2   352321536L
#define OFF_Vt2   402653184L
#define OFF_Vt3   452984832L    // [4096,512]

// activation slab offsets; each slab = [3][512][K]
#define AOFF_EG0  0L            // [512,1024]
#define AOFF_EG1  1572864L      // [512,4096]
#define AOFF_ED2  7864320L
#define AOFF_EG2  14155776L
#define AOFF_ED3  20447232L
#define AOFF_ED4  26738688L     // [512,512]
#define AOFF_X1   27525120L     // [512,4096]
#define AOFF_X2   33816576L
#define AOFF_X3   40108032L

// ---------------------------------------------------------------------------
__device__ __forceinline__ uint32_t smem_u32(const void* p) {
    uint32_t a;
    asm("{ .reg .u64 t; cvta.to.shared.u64 t, %1; cvt.u32.u64 %0, t; }"
        : "=r"(a) : "l"(p));
    return a;
}
#define CP16(dst, src) \
    asm volatile("cp.async.cg.shared.global [%0], [%1], 16;" \
                 :: "r"(dst), "l"(src) : "memory")
#define CP_COMMIT() asm volatile("cp.async.commit_group;" ::: "memory")
#define CP_WAIT1()  asm volatile("cp.async.wait_group 1;" ::: "memory")
#define CP_WAIT0()  asm volatile("cp.async.wait_group 0;" ::: "memory")

__device__ __forceinline__ void ldsm_x4(uint32_t (&r)[4], uint32_t addr) {
    asm volatile("ldmatrix.sync.aligned.m8n8.x4.shared.b16 {%0,%1,%2,%3}, [%4];"
                 : "=r"(r[0]), "=r"(r[1]), "=r"(r[2]), "=r"(r[3]) : "r"(addr));
}
__device__ __forceinline__ void mma_bf16(float (&c)[4], const uint32_t (&a)[4],
                                         uint32_t b0, uint32_t b1) {
    asm volatile(
        "mma.sync.aligned.m16n8k16.row.col.f32.bf16.bf16.f32 "
        "{%0,%1,%2,%3}, {%4,%5,%6,%7}, {%8,%9}, {%0,%1,%2,%3};"
        : "+f"(c[0]), "+f"(c[1]), "+f"(c[2]), "+f"(c[3])
        : "r"(a[0]), "r"(a[1]), "r"(a[2]), "r"(a[3]), "r"(b0), "r"(b1));
}

// ---------------------------------------------------------------------------
// GEMM: C[512,Nlim] = alpha * sum6( A_s @ B_s^T ) + g0*aux0 + g1*aux1
//       (+ optional bf16x3 split emission of C)
// 512 threads / 16 warps, warp tile 32x32 (4x4 warp grid on 128x128 tile).
// grid.z indexes the TG table; CTAs with bn >= Nlim exit (mixed-N batching).
// ---------------------------------------------------------------------------
struct TG {
    const bf16 *A1, *B1, *A2, *B2;
    long sA1, sB1, sA2, sB2;        // per-split slab strides
    int  lda1, ldb1, lda2, ldb2;    // row strides (elements)
    int  K1, K2;
    float* C; int ldc;
    const float* aux0; int ld0; float g0;
    const float* aux1; int ld1; float g1;
    float alpha;
    bf16* so; long sso; int ldso;   // optional split output [3][512][N]
    int  Nlim;
};
struct TGB { TG g[16]; };

#define TILE_B   10240            // 128 rows x 80B (32 bf16 + 8B pad)
#define STAGE_B  (6 * TILE_B)     // A0,A1,A2,B0,B1,B2
#define SMEM_MM  (3 * STAGE_B)    // 3-stage pipeline = 184320 B

__global__ __launch_bounds__(512, 1) void gemm_mma(TGB pb) {
    extern __shared__ char smem[];
    const TG& p = pb.g[blockIdx.z];
    const int bn = blockIdx.x * 128;
    if (bn >= p.Nlim) return;           // mixed-N batching early exit
    const uint32_t sb = smem_u32(smem);
    const int tid  = threadIdx.x;
    const int wid  = tid >> 5;
    const int lane = tid & 31;
    const int bm   = blockIdx.y * 128;
    const int wm   = (wid & 3) * 32;    // 4 row blocks
    const int wn   = (wid >> 2) * 32;   // 4 col blocks

    const int nk1 = p.K1 >> 5;
    const int nk  = (p.K1 + p.K2) >> 5;
    float* C = p.C;

    float acc[2][4][4];
#pragma unroll
    for (int i = 0; i < 2; i++)
#pragma unroll
        for (int j = 0; j < 4; j++)
#pragma unroll
            for (int q = 0; q < 4; q++) acc[i][j][q] = 0.0f;

    // loader: 512 threads, exactly one 16B transfer per tile per thread
    auto load_chunk = [&](int c, int s) {
        const bool seg2 = (c >= nk1);
        const bf16* Ab = seg2 ? p.A2 : p.A1;
        const bf16* Bb = seg2 ? p.B2 : p.B1;
        const long  sA = seg2 ? p.sA2 : p.sA1;
        const long  sB = seg2 ? p.sB2 : p.sB1;
        const int   la = seg2 ? p.lda2 : p.lda1;
        const int   lb = seg2 ? p.ldb2 : p.ldb1;
        const long  kcoff = (long)(seg2 ? c - nk1 : c) * 32;
        const uint32_t base = sb + s * STAGE_B;
        const int row = tid >> 2;
        const int seg = (tid & 3) * 16;
#pragma unroll
        for (int sp = 0; sp < 3; sp++) {
            const bf16* ga = Ab + sp * sA + kcoff;
            const bf16* gb = Bb + sp * sB + kcoff;
            CP16(base + sp * TILE_B + row * 80 + seg,
                 (const char*)(ga + (long)(bm + row) * la) + seg);
            CP16(base + (3 + sp) * TILE_B + row * 80 + seg,
                 (const char*)(gb + (long)(bn + row) * lb) + seg);
        }
        CP_COMMIT();
    };

    load_chunk(0, 0);
    load_chunk(1, 1);

#define LDA(F, abase, kk)                                                      \
    _Pragma("unroll")                                                          \
    for (int i = 0; i < 2; i++)                                                \
        ldsm_x4(F[i], (abase) + (uint32_t)(wm + 16 * i + (lane & 15)) * 80     \
                        + (kk) * 32 + (lane >> 4) * 16);
#define LDB(F, bbase, kk)                                                      \
    _Pragma("unroll")                                                          \
    for (int h = 0; h < 2; h++)                                                \
        ldsm_x4(F[h], (bbase) + (uint32_t)(wn + 16 * h + 8 * ((lane >> 4) & 1) \
                        + (lane & 7)) * 80 + (kk) * 32 + ((lane >> 3) & 1) * 16);
#define MMAS(AF, BF)                                                           \
    _Pragma("unroll")                                                          \
    for (int i = 0; i < 2; i++)                                                \
        _Pragma("unroll")                                                      \
        for (int j = 0; j < 4; j++)                                            \
            mma_bf16(acc[i][j], AF[i], BF[j >> 1][(j & 1) * 2],                \
                     BF[j >> 1][(j & 1) * 2 + 1]);

    for (int c = 0; c < nk; c++) {
        if (c + 1 < nk) CP_WAIT1(); else CP_WAIT0();
        __syncthreads();
        if (c + 2 < nk) load_chunk(c + 2, (c + 2) % 3);

        const uint32_t base = sb + (c % 3) * STAGE_B;
        const uint32_t a0 = base,              a1 = base + TILE_B,     a2 = base + 2 * TILE_B;
        const uint32_t b0 = base + 3 * TILE_B, b1 = base + 4 * TILE_B, b2 = base + 5 * TILE_B;
#pragma unroll
        for (int kk = 0; kk < 2; kk++) {
            // B-resident, A-streamed 6-product schedule:
            uint32_t B0[2][4], B1r[2][4], B2r[2][4], A[2][4];
            LDB(B0, b0, kk); LDB(B1r, b1, kk); LDB(B2r, b2, kk);
            LDA(A, a0, kk);                     // Ah
            MMAS(A, B0);                        // hi * hi
            MMAS(A, B1r);                       // hi * mid
            MMAS(A, B2r);                       // hi * lo
            LDA(A, a1, kk);                     // Am
            MMAS(A, B0);                        // mid * hi
            MMAS(A, B1r);                       // mid * mid
            LDA(A, a2, kk);                     // Al
            MMAS(A, B0);                        // lo * hi
        }
        // no trailing sync: stage (c+2)%3 was last read at chunk c-1, which
        // every warp finished before passing this chunk's top barrier.
    }
#undef LDA
#undef LDB
#undef MMAS

    // ---- epilogue ---------------------------------------------------------
    const int r0    = lane >> 2;
    const int cpair = (lane & 3) * 2;
#pragma unroll
    for (int i = 0; i < 2; i++) {
        const long gr = bm + wm + 16 * i + r0;
#pragma unroll
        for (int j = 0; j < 4; j++) {
            const int gc = bn + wn + 8 * j + cpair;
            float v[4];
            v[0] = p.alpha * acc[i][j][0];
            v[1] = p.alpha * acc[i][j][1];
            v[2] = p.alpha * acc[i][j][2];
            v[3] = p.alpha * acc[i][j][3];
            if (p.aux0) {
                const float2 u0 = *(const float2*)(p.aux0 + gr * p.ld0 + gc);
                const float2 u1 = *(const float2*)(p.aux0 + (gr + 8) * p.ld0 + gc);
                v[0] += p.g0 * u0.x; v[1] += p.g0 * u0.y;
                v[2] += p.g0 * u1.x; v[3] += p.g0 * u1.y;
            }
            if (p.aux1) {
                const float2 u0 = *(const float2*)(p.aux1 + gr * p.ld1 + gc);
                const float2 u1 = *(const float2*)(p.aux1 + (gr + 8) * p.ld1 + gc);
                v[0] += p.g1 * u0.x; v[1] += p.g1 * u0.y;
                v[2] += p.g1 * u1.x; v[3] += p.g1 * u1.y;
            }
            *(float2*)(C + gr * p.ldc + gc)       = make_float2(v[0], v[1]);
            *(float2*)(C + (gr + 8) * p.ldc + gc) = make_float2(v[2], v[3]);
            if (p.so) {                         // fused bf16x3 split emission
                bf16 h[4], m[4], l[4];
#pragma unroll
                for (int q = 0; q < 4; q++) {
                    h[q] = __float2bfloat16(v[q]);
                    const float r1 = v[q] - __bfloat162float(h[q]);
                    m[q] = __float2bfloat16(r1);
                    l[q] = __float2bfloat16(r1 - __bfloat162float(m[q]));
                }
                __nv_bfloat162 P;
                P.x = h[0]; P.y = h[1];
                *(__nv_bfloat162*)(p.so + gr * p.ldso + gc) = P;
                P.x = h[2]; P.y = h[3];
                *(__nv_bfloat162*)(p.so + (gr + 8) * p.ldso + gc) = P;
                P.x = m[0]; P.y = m[1];
                *(__nv_bfloat162*)(p.so + p.sso + gr * p.ldso + gc) = P;
                P.x = m[2]; P.y = m[3];
                *(__nv_bfloat162*)(p.so + p.sso + (gr + 8) * p.ldso + gc) = P;
                P.x = l[0]; P.y = l[1];
                *(__nv_bfloat162*)(p.so + 2 * p.sso + gr * p.ldso + gc) = P;
                P.x = l[2]; P.y = l[3];
                *(__nv_bfloat162*)(p.so + 2 * p.sso + (gr + 8) * p.ldso + gc) = P;
            }
        }
    }
}

// ---------------------------------------------------------------------------
// Split-K reduce: e = 0.5*ref - 0.5*sum_z P[z]; write float + bf16x3 splits
// ---------------------------------------------------------------------------
__global__ void reduce_k(const float* __restrict__ P, int nsplit,
                         const float* __restrict__ ref, int ldref,
                         float* __restrict__ out, int outoff, int N,
                         bf16* __restrict__ so, long sso) {
    const int idx = blockIdx.x * blockDim.x + threadIdx.x;
    if (idx >= 512 * N) return;
    const int  b    = idx / N;
    const int  f    = idx - b * N;
    const long slab = (long)512 * N;
    float s = 0.0f;
    for (int z = 0; z < nsplit; ++z) s += P[z * slab + idx];
    const float e = 0.5f * ref[(long)b * ldref + f] - 0.5f * s;
    out[(long)b * OUT_LD + outoff + f] = e;
    const bf16 h = __float2bfloat16(e);
    const float r1 = e - __bfloat162float(h);
    const bf16 m = __float2bfloat16(r1);
    so[idx]           = h;
    so[sso + idx]     = m;
    so[2 * sso + idx] = __float2bfloat16(r1 - __bfloat162float(m));
}

// ---------------------------------------------------------------------------
// splitters (weights / inputs, once per launch)
// ---------------------------------------------------------------------------
__global__ void split_k(const float* __restrict__ in, int ld, int rows, int cols,
                        bf16* __restrict__ out) {
    const long n = (long)rows * cols;
    const long idx = (long)blockIdx.x * blockDim.x + threadIdx.x;
    if (idx >= n) return;
    const int r = (int)(idx / cols), c = (int)(idx - (long)r * cols);
    const float a = in[(long)r * ld + c];
    const bf16 h = __float2bfloat16(a);
    const float f1 = a - __bfloat162float(h);
    const bf16 m = __float2bfloat16(f1);
    out[idx]         = h;
    out[n + idx]     = m;
    out[2 * n + idx] = __float2bfloat16(f1 - __bfloat162float(m));
}
__global__ void splitT_k(const float* __restrict__ in, int ldin, int K, int N,
                         bf16* __restrict__ out) {
    const long n = (long)N * K;
    const long idx = (long)blockIdx.x * blockDim.x + threadIdx.x;
    if (idx >= n) return;
    const int nn = (int)(idx / K), k = (int)(idx - (long)nn * K);
    const float a = in[(long)k * ldin + nn];
    const bf16 h = __float2bfloat16(a);
    const float f1 = a - __bfloat162float(h);
    const bf16 m = __float2bfloat16(f1);
    out[idx]         = h;
    out[n + idx]     = m;
    out[2 * n + idx] = __float2bfloat16(f1 - __bfloat162float(m));
}

// ---------------------------------------------------------------------------
// Analytic step 1 (carry all-zero):
//   eg0 = 0.5*xd ; ed1 = -c1h ; eg3 = -c2h ; ed4 = 0.5*yt ; rest stay 0.
// Also emits EG0/ED4 bf16x3 splits (consumed by step-2 Phase A).
// ---------------------------------------------------------------------------
__global__ void init_err_k(float* dout, const float* __restrict__ xd,
                           const float* __restrict__ yt) {
    const long N0 = 512L * 1024;         // eg0
    const long N1 = 512L * 4096;         // ed1 / eg3 each
    const long total = N0 + 2 * N1 + 512L * 512;
    const long idx = (long)blockIdx.x * blockDim.x + threadIdx.x;
    if (idx >= total) return;
    if (idx < N0) {                      // eg0 = 0.5*xd  (+ splits)
        const int b = (int)(idx >> 10), f = (int)(idx & 1023);
        const float e = 0.5f * xd[idx];
        dout[(long)b * OUT_LD + f] = e;
        const bf16 h = __float2bfloat16(e);
        const float r1 = e - __bfloat162float(h);
        const bf16 m = __float2bfloat16(r1);
        g_act[AOFF_EG0 + idx]           = h;
        g_act[AOFF_EG0 + 524288 + idx]  = m;
        g_act[AOFF_EG0 + 1048576 + idx] = __float2bfloat16(r1 - __bfloat162float(m));
    } else if (idx < N0 + N1) {          // ed1 = -c1h
        const long r = idx - N0;
        const int b = (int)(r >> 12), f = (int)(r & 4095);
        dout[(long)b * OUT_LD + 13312 + f] = -g_c1h[r];
    } else if (idx < N0 + 2 * N1) {      // eg3 = -c2h
        const long r = idx - N0 - N1;
        const int b = (int)(r >> 12), f = (int)(r & 4095);
        dout[(long)b * OUT_LD + 9216 + f] = -g_c2h[r];
    } else {                             // ed4 = 0.5*yt  (+ splits)
        const long r = idx - N0 - 2 * N1;
        const int b = (int)(r >> 9), f = (int)(r & 511);
        const float e = 0.5f * yt[r];
        dout[(long)b * OUT_LD + 25600 + f] = e;
        const bf16 h = __float2bfloat16(e);
        const float r1 = e - __bfloat162float(h);
        const bf16 m = __float2bfloat16(r1);
        g_act[AOFF_ED4 + r]          = h;
        g_act[AOFF_ED4 + 262144 + r] = m;
        g_act[AOFF_ED4 + 524288 + r] = __float2bfloat16(r1 - __bfloat162float(m));
    }
}

// ---------------------------------------------------------------------------
// LIF update; emits ed1/eg3 (float) and x1..3 bf16x3 splits
// ---------------------------------------------------------------------------
__global__ void lif_k(float* dout) {
    const long idx = (long)blockIdx.x * blockDim.x + threadIdx.x;
    if (idx >= 3L * S_LAYER) return;
    const int L = (int)(idx / S_LAYER);
    const int r = (int)(idx - (long)L * S_LAYER);

    const float tin = g_tin[idx];
    float j = g_state[idx];
    float v = g_state[3L * S_LAYER + idx];
    float x = g_state[6L * S_LAYER + idx];

    j = j + 0.25f * (tin - j);
    v = v + 0.05f * (j - v);
    const float spk = (v > 1.0f) ? 1.0f : 0.0f;
    v = v * (1.0f - spk);
    x = x * (1.0f - 0.025f) + spk;

    g_state[idx] = j;
    g_state[3L * S_LAYER + idx] = v;
    g_state[6L * S_LAYER + idx] = x;

    const long xb = AOFF_X1 + (long)L * 6291456L + r;
    const bf16 h = __float2bfloat16(x);
    const float f1 = x - __bfloat162float(h);
    const bf16 m = __float2bfloat16(f1);
    g_act[xb]            = h;
    g_act[xb + 2097152L] = m;
    g_act[xb + 4194304L] = __float2bfloat16(f1 - __bfloat162float(m));

    if (L == 0) {                         // ed1 = 0.5*x1 - c1h
        const int b = r >> 12, f = r & 4095;
        dout[(long)b * OUT_LD + 13312 + f] = 0.5f * x - g_c1h[r];
    } else if (L == 2) {                  // eg3 = 0.5*x3 - c2h
        const int b = r >> 12, f = r & 4095;
        dout[(long)b * OUT_LD + 9216 + f] = 0.5f * x - g_c2h[r];
    }
}

__global__ void zero_k(float* dout) {
    const long n1 = 9L * S_LAYER;
    const long n2 = 27525120L;            // act EG0..ED4 region
    const long n3 = 512L * OUT_LD;
    for (long i = (long)blockIdx.x * blockDim.x + threadIdx.x; i < n1 + n2 + n3;
         i += (long)gridDim.x * blockDim.x) {
        if (i < n1)            g_state[i] = 0.0f;
        else if (i < n1 + n2)  g_act[i - n1] = __float2bfloat16(0.0f);
        else                   dout[i - n1 - n2] = 0.0f;
    }
}

// ---------------------------------------------------------------------------
static TG make_tg(const bf16* A1, long sA1, int lda1,
                  const bf16* B1, long sB1, int ldb1, int K1,
                  const bf16* A2, long sA2, int lda2,
                  const bf16* B2, long sB2, int ldb2, int K2,
                  float* C, int ldc,
                  const float* a0, int l0, float g0,
                  const float* a1, int l1, float g1,
                  float alpha, int Nlim,
                  bf16* so = nullptr, long sso = 0, int ldso = 0) {
    TG p;
    p.A1 = A1; p.sA1 = sA1; p.lda1 = lda1;
    p.B1 = B1; p.sB1 = sB1; p.ldb1 = ldb1; p.K1 = K1;
    p.A2 = A2 ? A2 : A1; p.sA2 = sA2; p.lda2 = lda2;
    p.B2 = B2 ? B2 : B1; p.sB2 = sB2; p.ldb2 = ldb2; p.K2 = K2;
    p.C = C; p.ldc = ldc;
    p.aux0 = a0; p.ld0 = l0; p.g0 = g0;
    p.aux1 = a1; p.ld1 = l1; p.g1 = g1;
    p.alpha = alpha;
    p.so = so; p.sso = sso; p.ldso = ldso;
    p.Nlim = Nlim;
    return p;
}

static void launch_batch(const TG* tg, int nz, int maxN) {
    TGB pb{};
    for (int z = 0; z < nz; z++) pb.g[z] = tg[z];
    dim3 grid(maxN / 128, 4, nz);
    gemm_mma<<<grid, 512, SMEM_MM>>>(pb);
}

extern "C" void kernel_launch(void* const* d_in, const int* in_sizes, int n_in,
                              void* d_out, int out_size) {
    (void)in_sizes; (void)n_in; (void)out_size;
    const float* xd = (const float*)d_in[0];   // (512, 1024)
    const float* yt = (const float*)d_in[1];   // (512, 512)
    const float* W0 = (const float*)d_in[2];
    const float* V0 = (const float*)d_in[3];
    const float* W1 = (const float*)d_in[4];
    const float* V1 = (const float*)d_in[5];
    const float* W2 = (const float*)d_in[6];
    const float* V2 = (const float*)d_in[7];
    const float* W3 = (const float*)d_in[8];
    const float* V3 = (const float*)d_in[9];
    float* out = (float*)d_out;

    cudaFuncSetAttribute(gemm_mma, cudaFuncAttributeMaxDynamicSharedMemorySize, SMEM_MM);

    float *st, *tin, *c1h, *c2h, *pA, *pB; bf16 *w, *act, *io;
    cudaGetSymbolAddress((void**)&st,  g_state);
    cudaGetSymbolAddress((void**)&tin, g_tin);
    cudaGetSymbolAddress((void**)&c1h, g_c1h);
    cudaGetSymbolAddress((void**)&c2h, g_c2h);
    cudaGetSymbolAddress((void**)&w,   g_w);
    cudaGetSymbolAddress((void**)&act, g_act);
    cudaGetSymbolAddress((void**)&io,  g_io);
    cudaGetSymbolAddress((void**)&pA,  g_pA);
    cudaGetSymbolAddress((void**)&pB,  g_pB);

    float* x1 = st + 6L * S_LAYER;
    float* x2 = st + 7L * S_LAYER;
    float* x3 = st + 8L * S_LAYER;
    float* t1 = tin;
    float* t2 = tin + S_LAYER;
    float* t3 = tin + 2L * S_LAYER;

    float* eg1 = out + 1024;
    float* eg2 = out + 5120;
    float* eg3 = out + 9216;     // written by lif_k / init_err_k
    float* ed1 = out + 13312;    // written by lif_k / init_err_k
    float* ed2 = out + 17408;
    float* ed3 = out + 21504;

    // ---- setup; process-launch index 3 is gemm_mma (ncu lands there) ------
    zero_k<<<2048, 256>>>(out);                                                     // 0
    split_k<<<(512 * 1024 + 255) / 256, 256>>>(xd, 1024, 512, 1024, io);            // 1
    split_k<<<(4096 * 1024 + 255) / 256, 256>>>(V0, 1024, 4096, 1024, w + OFF_V0d); // 2
    {   // 3: c1h = 0.5 * xd @ V0^T   (N=4096, K=1024) — profiled launch
        TG g = make_tg(io, 524288, 1024, w + OFF_V0d, 4194304, 1024, 1024,
                       nullptr, 0, 0, nullptr, 0, 0, 0,
                       c1h, 4096, nullptr, 0, 0.f, nullptr, 0, 0.f, 0.5f, 4096);
        launch_batch(&g, 1, 4096);
    }
    split_k<<<(512 * 512  + 255) / 256, 256>>>(yt, 512,  512, 512,  io + 1572864);  // 4
    split_k<<<(4096 * 512  + 255) / 256, 256>>>(W3, 512,  4096, 512,  w + OFF_W3d); // 5
    {   // 6: c2h = 0.5 * yt @ W3^T   (N=4096, K=512)
        TG g = make_tg(io + 1572864, 262144, 512, w + OFF_W3d, 2097152, 512, 512,
                       nullptr, 0, 0, nullptr, 0, 0, 0,
                       c2h, 4096, nullptr, 0, 0.f, nullptr, 0, 0.f, 0.5f, 4096);
        launch_batch(&g, 1, 4096);
    }
    // 7: analytic step 1 (carry all-zero -> closed-form errors)
    init_err_k<<<(int)((512L * 1024 + 2 * 512L * 4096 + 512L * 512 + 255) / 256), 256>>>(out, xd, yt);

    split_k<<<(1024 * 4096 + 255) / 256, 256>>>(W0, 4096, 1024, 4096, w + OFF_W0d);
    split_k<<<(4096 * 4096 + 255) / 256, 256>>>(W1, 4096, 4096, 4096, w + OFF_W1d);
    split_k<<<(4096 * 4096 + 255) / 256, 256>>>(V1, 4096, 4096, 4096, w + OFF_V1d);
    split_k<<<(4096 * 4096 + 255) / 256, 256>>>(W2, 4096, 4096, 4096, w + OFF_W2d);
    split_k<<<(4096 * 4096 + 255) / 256, 256>>>(V2, 4096, 4096, 4096, w + OFF_V2d);
    split_k<<<(512  * 4096 + 255) / 256, 256>>>(V3, 4096, 512,  4096, w + OFF_V3d);
    splitT_k<<<(4096 * 1024 + 255) / 256, 256>>>(W0, 4096, 1024, 4096, w + OFF_Wt0);
    splitT_k<<<(4096 * 4096 + 255) / 256, 256>>>(W1, 4096, 4096, 4096, w + OFF_Wt1);
    splitT_k<<<(4096 * 4096 + 255) / 256, 256>>>(V1, 4096, 4096, 4096, w + OFF_Vt1);
    splitT_k<<<(4096 * 4096 + 255) / 256, 256>>>(W2, 4096, 4096, 4096, w + OFF_Wt2);
    splitT_k<<<(4096 * 4096 + 255) / 256, 256>>>(V2, 4096, 4096, 4096, w + OFF_Vt2);
    splitT_k<<<(4096 * 512  + 255) / 256, 256>>>(V3, 4096, 512,  4096, w + OFF_Vt3);

    // ---- steps 2..25 (step 1 done analytically) ----
    const int NUM_STEPS = 25;
    for (int t = 1; t < NUM_STEPS; t++) {
        // ---- Phase A: injected currents — ONE launch, z = 3 ----
        TG pa[3];
        pa[0] = make_tg(act + AOFF_EG0, 524288, 1024, w + OFF_Wt0, 4194304, 1024, 1024,
                        act + AOFF_ED2, 2097152, 4096, w + OFF_Vt1, 16777216, 4096, 4096,
                        t1, 4096, ed1, OUT_LD, -1.f, eg1, OUT_LD, -1.f, 1.f, 4096);
        pa[1] = make_tg(act + AOFF_EG1, 2097152, 4096, w + OFF_Wt1, 16777216, 4096, 4096,
                        act + AOFF_ED3, 2097152, 4096, w + OFF_Vt2, 16777216, 4096, 4096,
                        t2, 4096, ed2, OUT_LD, -1.f, eg2, OUT_LD, -1.f, 1.f, 4096);
        pa[2] = make_tg(act + AOFF_EG2, 2097152, 4096, w + OFF_Wt2, 16777216, 4096, 4096,
                        act + AOFF_ED4, 262144, 512,  w + OFF_Vt3, 2097152, 512, 512,
                        t3, 4096, ed3, OUT_LD, -1.f, eg3, OUT_LD, -1.f, 1.f, 4096);
        launch_batch(pa, 3, 4096);

        // ---- LIF update (+ ed1, eg3, x splits) ----
        lif_k<<<(3 * S_LAYER + 255) / 256, 256>>>(out);

        // ---- Phase B mega-batch: 4 mains + 4 eg0 chunks + 8 ed4 chunks ----
        TG pbt[16];
        pbt[0] = make_tg(act + AOFF_X2, 2097152, 4096, w + OFF_W1d, 16777216, 4096, 4096,
                         nullptr, 0, 0, nullptr, 0, 0, 0,
                         eg1, OUT_LD, x1, 4096, 0.5f, nullptr, 0, 0.f, -0.5f, 4096,
                         act + AOFF_EG1, 2097152, 4096);
        pbt[1] = make_tg(act + AOFF_X1, 2097152, 4096, w + OFF_V1d, 16777216, 4096, 4096,
                         nullptr, 0, 0, nullptr, 0, 0, 0,
                         ed2, OUT_LD, x2, 4096, 0.5f, nullptr, 0, 0.f, -0.5f, 4096,
                         act + AOFF_ED2, 2097152, 4096);
        pbt[2] = make_tg(act + AOFF_X3, 2097152, 4096, w + OFF_W2d, 16777216, 4096, 4096,
                         nullptr, 0, 0, nullptr, 0, 0, 0,
                         eg2, OUT_LD, x2, 4096, 0.5f, nullptr, 0, 0.f, -0.5f, 4096,
                         act + AOFF_EG2, 2097152, 4096);
        pbt[3] = make_tg(act + AOFF_X2, 2097152, 4096, w + OFF_V2d, 16777216, 4096, 4096,
                         nullptr, 0, 0, nullptr, 0, 0, 0,
                         ed3, OUT_LD, x3, 4096, 0.5f, nullptr, 0, 0.f, -0.5f, 4096,
                         act + AOFF_ED3, 2097152, 4096);
        for (int c = 0; c < 4; c++)          // eg0 split-K chunks (K=1024 each)
            pbt[4 + c] = make_tg(act + AOFF_X1 + c * 1024, 2097152, 4096,
                                 w + OFF_W0d + c * 1024, 4194304, 4096, 1024,
                                 nullptr, 0, 0, nullptr, 0, 0, 0,
                                 pA + (long)c * 524288, 1024,
                                 nullptr, 0, 0.f, nullptr, 0, 0.f, 1.f, 1024);
        for (int c = 0; c < 8; c++)          // ed4 split-K chunks (K=512 each)
            pbt[8 + c] = make_tg(act + AOFF_X3 + c * 512, 2097152, 4096,
                                 w + OFF_V3d + c * 512, 2097152, 4096, 512,
                                 nullptr, 0, 0, nullptr, 0, 0, 0,
                                 pB + (long)c * 262144, 512,
                                 nullptr, 0, 0.f, nullptr, 0, 0.f, 1.f, 512);
        launch_batch(pbt, 16, 4096);

        reduce_k<<<(512 * 1024 + 255) / 256, 256>>>(pA, 4, xd, 1024, out, 0, 1024,
                                                    act + AOFF_EG0, 524288);
        reduce_k<<<(512 * 512 + 255) / 256, 256>>>(pB, 8, yt, 512, out, 25600, 512,
                                                   act + AOFF_ED4, 262144);
    }
}